// round 16
// baseline (speedup 1.0000x reference)
#include <cuda_runtime.h>
#include <cuda_bf16.h>

// Problem constants (from reference)
#define NUM_IDS   100000
#define FEAT_DIM  512
#define BATCH     512
#define KNEG      100
#define MARGIN    0.03f

#define WARPS_PER_BLOCK 16
#define THREADS_MAIN    (WARPS_PER_BLOCK * 32)   // 512

#define HASH_SIZE 2048                            // 512 labels @ 25% load
#define HASH_MASK (HASH_SIZE - 1)
#define PPITCH    33    // 32 lanes + 1 pad -> conflict-free partials

// Scratch (no cudaMalloc allowed). g_done_counter is self-resetting: the
// last block of each launch zeroes it, so every graph replay starts at 0.
__device__ float        g_partials[BATCH];
__device__ unsigned int g_done_counter;   // zero-initialized at module load

__device__ __forceinline__ int clampi(int v, int lo, int hi) {
    return v < lo ? lo : (v > hi ? hi : v);
}

__device__ __forceinline__ unsigned int hash_id(int l) {
    return (((unsigned int)l * 2654435761u) >> 21) & HASH_MASK;
}

// L2-only load of a float4 (no L1 allocation — gathered rows have no L1 reuse)
__device__ __forceinline__ float4 ldcg4(const float4* p) {
    return __ldcg(p);
}

// Dot-product contribution of one 2KB row against u (registers)
#define DOT_ROW(ACC, P)                                                     \
    do {                                                                    \
        float4 v0 = ldcg4((P) + lane);                                      \
        float4 v1 = ldcg4((P) + lane + 32);                                 \
        float4 v2 = ldcg4((P) + lane + 64);                                 \
        float4 v3 = ldcg4((P) + lane + 96);                                 \
        float4 T;                                                           \
        T.x = v0.x * u0.x; T.y = v0.y * u0.y;                               \
        T.z = v0.z * u0.z; T.w = v0.w * u0.w;                               \
        T.x = fmaf(v1.x, u1.x, T.x); T.y = fmaf(v1.y, u1.y, T.y);           \
        T.z = fmaf(v1.z, u1.z, T.z); T.w = fmaf(v1.w, u1.w, T.w);           \
        T.x = fmaf(v2.x, u2.x, T.x); T.y = fmaf(v2.y, u2.y, T.y);           \
        T.z = fmaf(v2.z, u2.z, T.z); T.w = fmaf(v2.w, u2.w, T.w);           \
        T.x = fmaf(v3.x, u3.x, T.x); T.y = fmaf(v3.y, u3.y, T.y);           \
        T.z = fmaf(v3.z, u3.z, T.z); T.w = fmaf(v3.w, u3.w, T.w);           \
        ACC = (T.x + T.y) + (T.z + T.w);                                    \
    } while (0)

// ---------------------------------------------------------------------------
// Single kernel: one block (16 warps, 512 thr) per batch row b.
// Same algorithm as the 17.0us best (R14): per-block smem hash resolves the
// scatter (order-independent final contents -> replay-deterministic);
// loss = relu(g . (f - t) - MARGIN); 3-row DOT triples with L2-only loads;
// deferred reduction via padded smem partials; fused deterministic final sum.
// CHANGE: 512-thread blocks. At 64 regs the RF fits 2 blocks/SM = 32 resident
// warps (vs 27.7 when grid-limited at 3.46 x 8-warp blocks), raising in-
// flight gather bytes without adding block-churn (block count unchanged).
// ---------------------------------------------------------------------------
__global__ void __launch_bounds__(THREADS_MAIN, 2)
couple_loss_main(const float* __restrict__ ftr,
                 const float* __restrict__ tftr,
                 const int* __restrict__ label,
                 const float* __restrict__ protos,
                 const int* __restrict__ idH,
                 float* __restrict__ out) {
    const int b    = blockIdx.x;
    const int tid  = threadIdx.x;
    const int warp = tid >> 5;
    const int lane = tid & 31;

    __shared__ float4 sh_u[FEAT_DIM / 4];           // 2 KB: ftr[b]-tftr[b]
    __shared__ const float4* sh_row[KNEG];          // 800 B resolved ptrs
    __shared__ float sh_part[KNEG * PPITCH];        // 12.9 KB lane partials
    __shared__ int   hkey[HASH_SIZE];               // 8 KB
    __shared__ int   hval[HASH_SIZE];               // 8 KB (0=none, b+1)
    __shared__ float sh_red[128];
    __shared__ bool  is_last;

    // ---- Phase 1: hash init (all threads) + u build (threads 0..127) ----
#pragma unroll
    for (int j = 0; j < HASH_SIZE / THREADS_MAIN; ++j) {
        hkey[tid + j * THREADS_MAIN] = -1;
        hval[tid + j * THREADS_MAIN] = 0;
    }
    if (tid < FEAT_DIM / 4) {
        const float4* f4 = (const float4*)(ftr  + (size_t)b * FEAT_DIM);
        const float4* t4 = (const float4*)(tftr + (size_t)b * FEAT_DIM);
        float4 fv = f4[tid];
        float4 tv = t4[tid];
        sh_u[tid] = make_float4(fv.x - tv.x, fv.y - tv.y,
                                fv.z - tv.z, fv.w - tv.w);
    }
    __syncthreads();

    // ---- Phase 2: insert the 512 labels (one per thread; max-b wins) ----
    {
        const int l = clampi(label[tid], 0, NUM_IDS - 1);
        unsigned int idx = hash_id(l);
        for (;;) {
            const int prev = atomicCAS(&hkey[idx], -1, l);
            if (prev == -1 || prev == l) {
                atomicMax(&hval[idx], tid + 1);
                break;
            }
            idx = (idx + 1) & HASH_MASK;
        }
    }
    __syncthreads();

    // ---- Phase 3: resolve the 100 gather-row pointers ----
    if (tid < KNEG) {
        const int lab = clampi(label[b], 0, NUM_IDS - 1);
        const int neg = clampi(idH[lab * KNEG + tid], 0, NUM_IDS - 1);
        int bsrc = 0;
        unsigned int idx = hash_id(neg);
        for (;;) {
            const int k = hkey[idx];
            if (k == -1) break;               // not overridden
            if (k == neg) { bsrc = hval[idx]; break; }
            idx = (idx + 1) & HASH_MASK;
        }
        sh_row[tid] = (bsrc > 0)
            ? (const float4*)(tftr + (size_t)(bsrc - 1) * FEAT_DIM)
            : (const float4*)(protos + (size_t)neg * FEAT_DIM);
    }
    __syncthreads();

    // Keep u in registers for the whole sweep (4 float4 per lane)
    const float4 u0 = sh_u[lane];
    const float4 u1 = sh_u[lane + 32];
    const float4 u2 = sh_u[lane + 64];
    const float4 u3 = sh_u[lane + 96];

    // ---- Sweep: warp w handles rows == w (mod 16); THREE rows per iter ----
    // Triples (r, r+16, r+32) at r = w and r = w+48 cover rows 0..95;
    // tail rows 96..99 go to warps 0..3.
#pragma unroll
    for (int r = warp; r + 32 < KNEG; r += 3 * WARPS_PER_BLOCK) {
        const float4* __restrict__ p1 = sh_row[r];
        const float4* __restrict__ p2 = sh_row[r + 16];
        const float4* __restrict__ p3 = sh_row[r + 32];
        float s1, s2, s3;
        DOT_ROW(s1, p1);
        DOT_ROW(s2, p2);
        DOT_ROW(s3, p3);
        sh_part[(r)      * PPITCH + lane] = s1;
        sh_part[(r + 16) * PPITCH + lane] = s2;
        sh_part[(r + 32) * PPITCH + lane] = s3;
    }
    if (warp + 96 < KNEG) {                     // tail rows 96..99, warps 0-3
        const float4* __restrict__ p1 = sh_row[warp + 96];
        float s1;
        DOT_ROW(s1, p1);
        sh_part[(warp + 96) * PPITCH + lane] = s1;
    }
    __syncthreads();

    // ---- Deferred reduction: thread t (<100) sums row t's 32 partials ----
    float v = 0.f;
    if (tid < KNEG) {
        const float* rowp = &sh_part[tid * PPITCH];
        float acc0 = 0.f, acc1 = 0.f, acc2 = 0.f, acc3 = 0.f;
#pragma unroll
        for (int j = 0; j < 32; j += 4) {
            acc0 += rowp[j];     acc1 += rowp[j + 1];
            acc2 += rowp[j + 2]; acc3 += rowp[j + 3];
        }
        v = fmaxf((acc0 + acc1) + (acc2 + acc3) - MARGIN, 0.f);
    }
    if (tid < 128) sh_red[tid] = 0.f;
    __syncthreads();
    if (tid < KNEG) sh_red[tid] = v;
    __syncthreads();
    if (tid < 64) sh_red[tid] += sh_red[tid + 64];
    __syncthreads();
    if (tid < 32) {
        float s = sh_red[tid] + sh_red[tid + 32];
#pragma unroll
        for (int off = 16; off > 0; off >>= 1)
            s += __shfl_xor_sync(0xffffffffu, s, off);
        if (tid == 0) {
            g_partials[b] = s;
            __threadfence();
            unsigned int prev = atomicAdd(&g_done_counter, 1u);
            is_last = (prev == (unsigned int)(BATCH - 1));
        }
    }
    __syncthreads();

    // ---- Last block: reduce the 512 partials, reset counter for replay ----
    if (is_last) {
        if (tid == 0) g_done_counter = 0u;   // all blocks already arrived
        __threadfence();
        __shared__ float sh2[THREADS_MAIN];
        sh2[tid] = g_partials[tid];          // one partial per thread
        __syncthreads();
#pragma unroll
        for (int off = THREADS_MAIN / 2; off > 0; off >>= 1) {
            if (tid < off) sh2[tid] += sh2[tid + off];
            __syncthreads();
        }
        if (tid == 0)
            out[0] = sh2[0] * (1.0f / (float)(BATCH * KNEG));
    }
}

// ---------------------------------------------------------------------------
extern "C" void kernel_launch(void* const* d_in, const int* in_sizes, int n_in,
                              void* d_out, int out_size) {
    const float* ftr    = (const float*)d_in[0];
    const float* tftr   = (const float*)d_in[1];
    const int*   label  = (const int*)d_in[2];
    const float* protos = (const float*)d_in[3];
    const int*   idH    = (const int*)d_in[4];
    float* out = (float*)d_out;

    couple_loss_main<<<BATCH, THREADS_MAIN>>>(ftr, tftr, label, protos,
                                              idH, out);
}

// round 17
// speedup vs baseline: 1.1788x; 1.1788x over previous
#include <cuda_runtime.h>
#include <cuda_bf16.h>

// Problem constants (from reference)
#define NUM_IDS   100000
#define FEAT_DIM  512
#define BATCH     512
#define KNEG      100
#define MARGIN    0.03f

#define WARPS_PER_BLOCK 8
#define THREADS_MAIN    (WARPS_PER_BLOCK * 32)   // 256

#define HASH_SIZE 2048                            // 512 labels @ 25% load
#define HASH_MASK (HASH_SIZE - 1)
#define PPITCH    33    // 32 lanes + 1 pad -> conflict-free partials

// Scratch (no cudaMalloc allowed). g_done_counter is self-resetting: the
// last block of each launch zeroes it, so every graph replay starts at 0.
__device__ float        g_partials[BATCH];
__device__ unsigned int g_done_counter;   // zero-initialized at module load

__device__ __forceinline__ int clampi(int v, int lo, int hi) {
    return v < lo ? lo : (v > hi ? hi : v);
}

__device__ __forceinline__ unsigned int hash_id(int l) {
    return (((unsigned int)l * 2654435761u) >> 21) & HASH_MASK;
}

// L2-only load of a float4 (no L1 allocation — gathered rows have no L1 reuse)
__device__ __forceinline__ float4 ldcg4(const float4* p) {
    return __ldcg(p);
}

// Dot-product contribution of one 2KB row against u (registers)
#define DOT_ROW(ACC, P)                                                     \
    do {                                                                    \
        float4 v0 = ldcg4((P) + lane);                                      \
        float4 v1 = ldcg4((P) + lane + 32);                                 \
        float4 v2 = ldcg4((P) + lane + 64);                                 \
        float4 v3 = ldcg4((P) + lane + 96);                                 \
        float4 T;                                                           \
        T.x = v0.x * u0.x; T.y = v0.y * u0.y;                               \
        T.z = v0.z * u0.z; T.w = v0.w * u0.w;                               \
        T.x = fmaf(v1.x, u1.x, T.x); T.y = fmaf(v1.y, u1.y, T.y);           \
        T.z = fmaf(v1.z, u1.z, T.z); T.w = fmaf(v1.w, u1.w, T.w);           \
        T.x = fmaf(v2.x, u2.x, T.x); T.y = fmaf(v2.y, u2.y, T.y);           \
        T.z = fmaf(v2.z, u2.z, T.z); T.w = fmaf(v2.w, u2.w, T.w);           \
        T.x = fmaf(v3.x, u3.x, T.x); T.y = fmaf(v3.y, u3.y, T.y);           \
        T.z = fmaf(v3.z, u3.z, T.z); T.w = fmaf(v3.w, u3.w, T.w);           \
        ACC = (T.x + T.y) + (T.z + T.w);                                    \
    } while (0)

// ---------------------------------------------------------------------------
// Single kernel: one block (8 warps, 256 thr) per batch row b — the R14
// champion shape (17.0us), plus PREAMBLE LATENCY HIDING: with grid=512 every
// block is resident in ONE wave, so the block preamble sits on the critical
// path exactly once. All global reads (hash labels, label[b], idH negatives,
// f/t feature rows) are issued at the very top of the kernel into registers;
// the dependent smem hash phases then overlap their ~1200cyc of latency.
//
// Scatter semantics resolved per block via a smem hash (order-independent
// final contents -> replay-deterministic). loss = relu(g.(f-t) - MARGIN).
// Hot loop: 3 rows per warp iteration (12 LDG.128 in flight, L2-only loads),
// deferred reduction via padded smem partials, fused deterministic final sum.
// ---------------------------------------------------------------------------
__global__ void __launch_bounds__(THREADS_MAIN, 4)
couple_loss_main(const float* __restrict__ ftr,
                 const float* __restrict__ tftr,
                 const int* __restrict__ label,
                 const float* __restrict__ protos,
                 const int* __restrict__ idH,
                 float* __restrict__ out) {
    const int b    = blockIdx.x;
    const int tid  = threadIdx.x;
    const int warp = tid >> 5;
    const int lane = tid & 31;

    __shared__ float4 sh_u[FEAT_DIM / 4];           // 2 KB: ftr[b]-tftr[b]
    __shared__ const float4* sh_row[KNEG];          // 800 B resolved ptrs
    __shared__ float sh_part[KNEG * PPITCH];        // 12.9 KB lane partials
    __shared__ int   hkey[HASH_SIZE];               // 8 KB
    __shared__ int   hval[HASH_SIZE];               // 8 KB (0=none, b+1)
    __shared__ float sh_red[128];
    __shared__ bool  is_last;

    // ---- Phase 0: issue ALL global loads up front (latency overlap) ----
    const int l0 = clampi(__ldg(&label[tid]),       0, NUM_IDS - 1);
    const int l1 = clampi(__ldg(&label[tid + 256]), 0, NUM_IDS - 1);
    const int lab = clampi(__ldg(&label[b]), 0, NUM_IDS - 1);
    int neg = 0;
    if (tid < KNEG)
        neg = clampi(__ldg(&idH[(size_t)lab * KNEG + tid]), 0, NUM_IDS - 1);
    float4 fv = make_float4(0.f, 0.f, 0.f, 0.f);
    float4 tv = make_float4(0.f, 0.f, 0.f, 0.f);
    if (tid < FEAT_DIM / 4) {
        fv = ((const float4*)(ftr  + (size_t)b * FEAT_DIM))[tid];
        tv = ((const float4*)(tftr + (size_t)b * FEAT_DIM))[tid];
    }

    // ---- Phase 1: hash init (smem stores overlap the loads above) ----
#pragma unroll
    for (int j = 0; j < HASH_SIZE / THREADS_MAIN; ++j) {
        hkey[tid + j * THREADS_MAIN] = -1;
        hval[tid + j * THREADS_MAIN] = 0;
    }
    if (tid < FEAT_DIM / 4)
        sh_u[tid] = make_float4(fv.x - tv.x, fv.y - tv.y,
                                fv.z - tv.z, fv.w - tv.w);
    __syncthreads();

    // ---- Phase 2: insert the 512 labels (last-write-wins via max b) ----
    {
        unsigned int idx = hash_id(l0);
        for (;;) {
            const int prev = atomicCAS(&hkey[idx], -1, l0);
            if (prev == -1 || prev == l0) {
                atomicMax(&hval[idx], tid + 1);
                break;
            }
            idx = (idx + 1) & HASH_MASK;
        }
        idx = hash_id(l1);
        for (;;) {
            const int prev = atomicCAS(&hkey[idx], -1, l1);
            if (prev == -1 || prev == l1) {
                atomicMax(&hval[idx], tid + 256 + 1);
                break;
            }
            idx = (idx + 1) & HASH_MASK;
        }
    }
    __syncthreads();

    // ---- Phase 3: resolve the 100 gather-row pointers (smem-only) ----
    if (tid < KNEG) {
        int bsrc = 0;
        unsigned int idx = hash_id(neg);
        for (;;) {
            const int k = hkey[idx];
            if (k == -1) break;               // not overridden
            if (k == neg) { bsrc = hval[idx]; break; }
            idx = (idx + 1) & HASH_MASK;
        }
        sh_row[tid] = (bsrc > 0)
            ? (const float4*)(tftr + (size_t)(bsrc - 1) * FEAT_DIM)
            : (const float4*)(protos + (size_t)neg * FEAT_DIM);
    }
    __syncthreads();

    // Keep u in registers for the whole sweep (4 float4 per lane)
    const float4 u0 = sh_u[lane];
    const float4 u1 = sh_u[lane + 32];
    const float4 u2 = sh_u[lane + 64];
    const float4 u3 = sh_u[lane + 96];

    // ---- Sweep: warp w handles rows == w (mod 8); THREE rows per iter ----
    // Triples at base r = w + 24j cover rows w..w+88; tail row w+96 for w<4.
    for (int r = warp; r + 16 < KNEG; r += 3 * WARPS_PER_BLOCK) {
        const float4* __restrict__ p1 = sh_row[r];
        const float4* __restrict__ p2 = sh_row[r + 8];
        const float4* __restrict__ p3 = sh_row[r + 16];
        float s1, s2, s3;
        DOT_ROW(s1, p1);
        DOT_ROW(s2, p2);
        DOT_ROW(s3, p3);
        sh_part[(r)      * PPITCH + lane] = s1;
        sh_part[(r + 8)  * PPITCH + lane] = s2;
        sh_part[(r + 16) * PPITCH + lane] = s3;
    }
    if (warp + 96 < KNEG) {                     // tail rows 96..99, warps 0-3
        const float4* __restrict__ p1 = sh_row[warp + 96];
        float s1;
        DOT_ROW(s1, p1);
        sh_part[(warp + 96) * PPITCH + lane] = s1;
    }
    __syncthreads();

    // ---- Deferred reduction: thread t (<100) sums row t's 32 partials ----
    float v = 0.f;
    if (tid < KNEG) {
        const float* rowp = &sh_part[tid * PPITCH];
        float acc0 = 0.f, acc1 = 0.f, acc2 = 0.f, acc3 = 0.f;
#pragma unroll
        for (int j = 0; j < 32; j += 4) {
            acc0 += rowp[j];     acc1 += rowp[j + 1];
            acc2 += rowp[j + 2]; acc3 += rowp[j + 3];
        }
        v = fmaxf((acc0 + acc1) + (acc2 + acc3) - MARGIN, 0.f);
    }
    if (tid < 128) sh_red[tid] = 0.f;
    __syncthreads();
    if (tid < KNEG) sh_red[tid] = v;
    __syncthreads();
    if (tid < 64) sh_red[tid] += sh_red[tid + 64];
    __syncthreads();
    if (tid < 32) {
        float s = sh_red[tid] + sh_red[tid + 32];
#pragma unroll
        for (int off = 16; off > 0; off >>= 1)
            s += __shfl_xor_sync(0xffffffffu, s, off);
        if (tid == 0) {
            g_partials[b] = s;
            __threadfence();
            unsigned int prev = atomicAdd(&g_done_counter, 1u);
            is_last = (prev == (unsigned int)(BATCH - 1));
        }
    }
    __syncthreads();

    // ---- Last block: reduce the 512 partials, reset counter for replay ----
    if (is_last) {
        if (tid == 0) g_done_counter = 0u;   // all blocks already arrived
        __threadfence();
        __shared__ float sh2[THREADS_MAIN];
        float acc = 0.f;
        for (int i = tid; i < BATCH; i += THREADS_MAIN) acc += g_partials[i];
        sh2[tid] = acc;
        __syncthreads();
#pragma unroll
        for (int off = THREADS_MAIN / 2; off > 0; off >>= 1) {
            if (tid < off) sh2[tid] += sh2[tid + off];
            __syncthreads();
        }
        if (tid == 0)
            out[0] = sh2[0] * (1.0f / (float)(BATCH * KNEG));
    }
}

// ---------------------------------------------------------------------------
extern "C" void kernel_launch(void* const* d_in, const int* in_sizes, int n_in,
                              void* d_out, int out_size) {
    const float* ftr    = (const float*)d_in[0];
    const float* tftr   = (const float*)d_in[1];
    const int*   label  = (const int*)d_in[2];
    const float* protos = (const float*)d_in[3];
    const int*   idH    = (const int*)d_in[4];
    float* out = (float*)d_out;

    couple_loss_main<<<BATCH, THREADS_MAIN>>>(ftr, tftr, label, protos,
                                              idH, out);
}